// round 9
// baseline (speedup 1.0000x reference)
#include <cuda_runtime.h>
#include <cuda_bf16.h>
#include <math.h>
#include <stdint.h>

#define BATCH 2
#define TSEQ  2048
#define DM    1024
#define NH    16
#define DH    64
#define MTOT  (BATCH*TSEQ)   // 4096

// ---------------- scratch (device globals; no allocation allowed) ----------
__device__ __align__(16) __nv_bfloat16 g_qh[(size_t)BATCH*NH*TSEQ*DH];
__device__ __align__(16) __nv_bfloat16 g_ql[(size_t)BATCH*NH*TSEQ*DH];
__device__ __align__(16) __nv_bfloat16 g_kh[(size_t)BATCH*NH*TSEQ*DH];
__device__ __align__(16) __nv_bfloat16 g_kl[(size_t)BATCH*NH*TSEQ*DH];
__device__ __align__(16) __nv_bfloat16 g_vh[(size_t)BATCH*NH*TSEQ*DH];
__device__ __align__(16) __nv_bfloat16 g_vl[(size_t)BATCH*NH*TSEQ*DH];

__device__ __align__(16) __nv_bfloat16 g_xh[(size_t)MTOT*DM];
__device__ __align__(16) __nv_bfloat16 g_xl[(size_t)MTOT*DM];
__device__ __align__(16) __nv_bfloat16 g_wh[(size_t)3*DM*DM];  // [Wk;Wq;Wv] (q<-Wk swap!)
__device__ __align__(16) __nv_bfloat16 g_wl[(size_t)3*DM*DM];
__device__ __align__(16) __nv_bfloat16 g_ch[(size_t)MTOT*DM];
__device__ __align__(16) __nv_bfloat16 g_cl[(size_t)MTOT*DM];
__device__ __align__(16) __nv_bfloat16 g_woh[(size_t)DM*DM];
__device__ __align__(16) __nv_bfloat16 g_wol[(size_t)DM*DM];

// ---------------- helpers ---------------------------------------------------
__device__ __forceinline__ uint32_t smem_u32(const void* p) {
    uint32_t a;
    asm("{ .reg .u64 t; cvta.to.shared.u64 t, %1; cvt.u32.u64 %0, t; }"
        : "=r"(a) : "l"(p));
    return a;
}
__device__ __forceinline__ void cp_async16(uint32_t dst, const void* src) {
    asm volatile("cp.async.cg.shared.global [%0], [%1], 16;"
                 :: "r"(dst), "l"(src) : "memory");
}
__device__ __forceinline__ void cp_commit() {
    asm volatile("cp.async.commit_group;" ::: "memory");
}
__device__ __forceinline__ void cp_wait_all() {
    asm volatile("cp.async.wait_group 0;" ::: "memory");
}
__device__ __forceinline__ void ldsm4(uint32_t* r, uint32_t a) {
    asm volatile("ldmatrix.sync.aligned.m8n8.x4.shared.b16 {%0,%1,%2,%3}, [%4];"
                 : "=r"(r[0]), "=r"(r[1]), "=r"(r[2]), "=r"(r[3]) : "r"(a));
}
__device__ __forceinline__ void ldsm4t(uint32_t* r, uint32_t a) {
    asm volatile("ldmatrix.sync.aligned.m8n8.x4.trans.shared.b16 {%0,%1,%2,%3}, [%4];"
                 : "=r"(r[0]), "=r"(r[1]), "=r"(r[2]), "=r"(r[3]) : "r"(a));
}
__device__ __forceinline__ void mma_bf16(float* c, const uint32_t* a, const uint32_t* b) {
    asm volatile(
        "mma.sync.aligned.m16n8k16.row.col.f32.bf16.bf16.f32 "
        "{%0,%1,%2,%3}, {%4,%5,%6,%7}, {%8,%9}, {%0,%1,%2,%3};"
        : "+f"(c[0]), "+f"(c[1]), "+f"(c[2]), "+f"(c[3])
        : "r"(a[0]), "r"(a[1]), "r"(a[2]), "r"(a[3]), "r"(b[0]), "r"(b[1]));
}
__device__ __forceinline__ uint32_t cvt2(float v_hi, float v_lo) {
    uint32_t r;
    asm("cvt.rn.bf16x2.f32 %0, %1, %2;" : "=r"(r) : "f"(v_hi), "f"(v_lo));
    return r;
}
__device__ __forceinline__ void split2(float v0, float v1, uint32_t& hi, uint32_t& lo) {
    hi = cvt2(v1, v0);
    float h0 = __uint_as_float(hi << 16);
    float h1 = __uint_as_float(hi & 0xffff0000u);
    lo = cvt2(v1 - h1, v0 - h0);
}
__device__ __forceinline__ uint32_t swz(int row, int colb) {
    uint32_t off = row * 128 + colb;
    return off ^ ((off >> 3) & 0x70);
}

// ---------------- merged fp32 -> bf16 hi/lo split (5 segments) --------------
#define XB ((MTOT*DM/4)/256)     // 4096 blocks
#define WB ((DM*DM/4)/256)       // 1024 blocks

__global__ void __launch_bounds__(256) split5_kernel(
    const float* __restrict__ x,  const float* __restrict__ Wk,
    const float* __restrict__ Wq, const float* __restrict__ Wv,
    const float* __restrict__ Wo,
    __nv_bfloat16* __restrict__ xh, __nv_bfloat16* __restrict__ xl,
    __nv_bfloat16* __restrict__ wh, __nv_bfloat16* __restrict__ wl,
    __nv_bfloat16* __restrict__ woh, __nv_bfloat16* __restrict__ wol)
{
    int blk = blockIdx.x;
    const float* src;
    __nv_bfloat16 *dh, *dl;
    int i;
    if (blk < XB) {
        src = x; dh = xh; dl = xl;
        i = blk * 256 + threadIdx.x;
    } else {
        int wseg = (blk - XB) / WB;        // 0..3
        int wblk = (blk - XB) % WB;
        i = wblk * 256 + threadIdx.x;
        if (wseg == 0)      { src = Wk; dh = wh;            dl = wl; }
        else if (wseg == 1) { src = Wq; dh = wh + DM*DM;    dl = wl + DM*DM; }
        else if (wseg == 2) { src = Wv; dh = wh + 2*DM*DM;  dl = wl + 2*DM*DM; }
        else                { src = Wo; dh = woh;           dl = wol; }
    }
    float4 v = ((const float4*)src)[i];
    __nv_bfloat16 h[4], l[4];
    float f[4] = {v.x, v.y, v.z, v.w};
#pragma unroll
    for (int j = 0; j < 4; j++) {
        h[j] = __float2bfloat16(f[j]);
        l[j] = __float2bfloat16(f[j] - __bfloat162float(h[j]));
    }
    *(uint2*)(dh + (size_t)i*4) = *(uint2*)h;
    *(uint2*)(dl + (size_t)i*4) = *(uint2*)l;
}

// ---------------------------------------------------------------------------
// Split-bf16 GEMM on HMMA, software-pipelined fragment loads.
// MODE 0: fused QKV -> bf16 hi/lo head-major (scale folded into q).
// MODE 1: fp32 out + bias.
// ---------------------------------------------------------------------------
#define GK       DM
#define BK       64
#define NCHUNK   (GK/BK)
#define TILE_B   (128*128)
#define BUF_B    (4*TILE_B)
#define GEMM_SMEM (2*BUF_B)     // 131072

template<int MODE>
__global__ void __launch_bounds__(256, 1) mma_gemm(
    const __nv_bfloat16* __restrict__ Ah, const __nv_bfloat16* __restrict__ Al,
    const __nv_bfloat16* __restrict__ Bh, const __nv_bfloat16* __restrict__ Bl,
    __nv_bfloat16* __restrict__ qh, __nv_bfloat16* __restrict__ ql,
    __nv_bfloat16* __restrict__ kh, __nv_bfloat16* __restrict__ kl,
    __nv_bfloat16* __restrict__ vh, __nv_bfloat16* __restrict__ vl,
    float* __restrict__ out, const float* __restrict__ bias)
{
    extern __shared__ char smem[];
    const uint32_t sb = smem_u32(smem);
    const int tid  = threadIdx.x;
    const int lane = tid & 31;
    const int w    = tid >> 5;
    const int m0   = blockIdx.y * 128;
    const int n0   = blockIdx.x * 128;

    const __nv_bfloat16* srcs[4] = {Ah + (size_t)m0*GK, Al + (size_t)m0*GK,
                                    Bh + (size_t)n0*GK, Bl + (size_t)n0*GK};

    auto issue_chunk = [&](int buf, int k0) {
        uint32_t dbase = sb + buf * BUF_B;
#pragma unroll
        for (int t = 0; t < 4; t++) {
            const __nv_bfloat16* src = srcs[t] + k0;
            uint32_t tb = dbase + t * TILE_B;
#pragma unroll
            for (int r2 = 0; r2 < 4; r2++) {
                int id  = tid + 256 * r2;
                int row = id >> 3;
                int c16 = id & 7;
                cp_async16(tb + swz(row, c16 * 16), src + (size_t)row*GK + c16*8);
            }
        }
        cp_commit();
    };

    float acc[2][8][4];
#pragma unroll
    for (int mt = 0; mt < 2; mt++)
#pragma unroll
        for (int nt = 0; nt < 8; nt++)
#pragma unroll
            for (int e = 0; e < 4; e++) acc[mt][nt][e] = 0.0f;

    const int mr  = (w & 3) * 32;
    const int nc0 = (w >> 2) * 64;
    const int quad = lane >> 3;
    const int l7   = lane & 7;
    const int a_row_off = (quad & 1) * 8 + l7;
    const int a_col_off = (quad >> 1) * 16;
    const int b_row_off = (quad >> 1) * 8 + l7;
    const int b_col_off = (quad & 1) * 16;

    issue_chunk(0, 0);

    for (int c = 0; c < NCHUNK; c++) {
        const int b = c & 1;
        cp_wait_all();
        __syncthreads();
        if (c + 1 < NCHUNK) issue_chunk(b ^ 1, (c + 1) * BK);

        const uint32_t pAh = sb + b*BUF_B;
        const uint32_t pAl = pAh + TILE_B;
        const uint32_t pBh = pAh + 2*TILE_B;
        const uint32_t pBl = pAh + 3*TILE_B;

        auto load_bf = [&](uint32_t (*dst)[2], uint32_t pbase, int ks) {
#pragma unroll
            for (int ng = 0; ng < 4; ng++) {
                uint32_t t4[4];
                ldsm4(t4, pbase + swz(nc0 + ng*16 + b_row_off, ks*32 + b_col_off));
                dst[ng*2][0] = t4[0]; dst[ng*2][1] = t4[1];
                dst[ng*2+1][0] = t4[2]; dst[ng*2+1][1] = t4[3];
            }
        };

        // preload all A-hi fragments for this chunk (8 ldsm)
        uint32_t aH[4][2][4];
#pragma unroll
        for (int ks = 0; ks < 4; ks++)
#pragma unroll
            for (int mt = 0; mt < 2; mt++)
                ldsm4(aH[ks][mt], pAh + swz(mr + mt*16 + a_row_off,
                                            ks*32 + a_col_off));

        uint32_t bF[2][8][2], bL[8][2], aL[2][2][4];
        load_bf(bF[0], pBh, 0);

#pragma unroll
        for (int ks = 0; ks < 4; ks++) {
            const int cur = ks & 1;
            // issue loads whose consumers are 16+ MMAs away
#pragma unroll
            for (int mt = 0; mt < 2; mt++)
                ldsm4(aL[cur][mt], pAl + swz(mr + mt*16 + a_row_off,
                                             ks*32 + a_col_off));
            load_bf(bL, pBl, ks);
            // hh
#pragma unroll
            for (int mt = 0; mt < 2; mt++)
#pragma unroll
                for (int nt = 0; nt < 8; nt++)
                    mma_bf16(acc[mt][nt], aH[ks][mt], bF[cur][nt]);
            if (ks < 3) load_bf(bF[cur ^ 1], pBh, ks + 1);
            // lh
#pragma unroll
            for (int mt = 0; mt < 2; mt++)
#pragma unroll
                for (int nt = 0; nt < 8; nt++)
                    mma_bf16(acc[mt][nt], aL[cur][mt], bF[cur][nt]);
            // hl
#pragma unroll
            for (int mt = 0; mt < 2; mt++)
#pragma unroll
                for (int nt = 0; nt < 8; nt++)
                    mma_bf16(acc[mt][nt], aH[ks][mt], bL[nt]);
        }
        __syncthreads();
    }

    // ---- epilogue ----
#pragma unroll
    for (int mt = 0; mt < 2; mt++) {
#pragma unroll
        for (int half = 0; half < 2; half++) {
            const int m = m0 + mr + mt*16 + (lane >> 2) + half*8;
#pragma unroll
            for (int nt = 0; nt < 8; nt++) {
                const int n = n0 + nc0 + nt*8 + (lane & 3)*2;
                const float c0 = acc[mt][nt][half*2 + 0];
                const float c1 = acc[mt][nt][half*2 + 1];
                if (MODE == 0) {
                    const int bb  = m >> 11;
                    const int t   = m & 2047;
                    const int mat = n >> 10;
                    const int np  = n & 1023;
                    const float sc = (mat == 0) ? 0.125f : 1.0f;
                    uint32_t hi, lo;
                    split2(c0*sc, c1*sc, hi, lo);
                    __nv_bfloat16* ph = (mat == 0) ? qh : ((mat == 1) ? kh : vh);
                    __nv_bfloat16* pl = (mat == 0) ? ql : ((mat == 1) ? kl : vl);
                    size_t idx = ((size_t)(bb*NH + (np >> 6)) * TSEQ + t) * DH + (np & 63);
                    *(uint32_t*)(ph + idx) = hi;
                    *(uint32_t*)(pl + idx) = lo;
                } else {
                    float* p = out + (size_t)m * DM + n;
                    p[0] = c0 + __ldg(bias + n);
                    p[1] = c1 + __ldg(bias + n + 1);
                }
            }
        }
    }
}

// ---------------------------------------------------------------------------
// Causal flash attention on HMMA, split-bf16, software-pipelined fragments.
// 128 queries/block, 8 warps, 64-key double-buffered chunks, longest-first.
// ---------------------------------------------------------------------------
#define AKV   8192
#define ABUF  (4*AKV)
#define AQ_OFF (2*ABUF)
#define ATTN_SMEM (2*ABUF + 2*16384)   // 98304

__global__ void __launch_bounds__(256, 1) attn_mma(
    const __nv_bfloat16* __restrict__ qh_g, const __nv_bfloat16* __restrict__ ql_g,
    const __nv_bfloat16* __restrict__ kh_g, const __nv_bfloat16* __restrict__ kl_g,
    const __nv_bfloat16* __restrict__ vh_g, const __nv_bfloat16* __restrict__ vl_g,
    __nv_bfloat16* __restrict__ ch_g, __nv_bfloat16* __restrict__ cl_g)
{
    extern __shared__ char smem[];
    const uint32_t sb = smem_u32(smem);
    const int tid  = threadIdx.x;
    const int lane = tid & 31;
    const int w    = tid >> 5;
    const int qt   = (TSEQ/128 - 1) - blockIdx.x;   // longest blocks first
    const int bh   = blockIdx.y;
    const int g    = lane >> 2;
    const int tig  = lane & 3;
    const int quad = lane >> 3;
    const int l7   = lane & 7;
    const int a_row  = (quad & 1) * 8 + l7;
    const int a_colb = (quad >> 1) * 16;
    const int b_row  = (quad >> 1) * 8 + l7;
    const int b_colb = (quad & 1) * 16;
    const int v_row  = (quad & 1) * 8 + l7;
    const int v_colb = (quad >> 1) * 16;

    const size_t base = (size_t)bh * TSEQ * DH;
    const int rowbase = qt * 128 + w * 16;

    auto issue_kv = [&](int buf, int key0) {
        uint32_t db = sb + buf * ABUF;
        const __nv_bfloat16* srcs[4] = {kh_g, kl_g, vh_g, vl_g};
#pragma unroll
        for (int t4 = 0; t4 < 4; t4++) {
#pragma unroll
            for (int r = 0; r < 2; r++) {
                int id  = tid + 256 * r;
                int row = id >> 3;
                int c16 = id & 7;
                cp_async16(db + t4*AKV + swz(row, c16*16),
                           srcs[t4] + base + (size_t)(key0 + row)*DH + c16*8);
            }
        }
    };

#pragma unroll
    for (int r = 0; r < 4; r++) {
        int id  = tid + 256 * r;
        int row = id >> 3;
        int c16 = id & 7;
        cp_async16(sb + AQ_OFF         + swz(row, c16*16),
                   qh_g + base + (size_t)(qt*128 + row)*DH + c16*8);
        cp_async16(sb + AQ_OFF + 16384 + swz(row, c16*16),
                   ql_g + base + (size_t)(qt*128 + row)*DH + c16*8);
    }
    issue_kv(0, 0);
    cp_commit();

    float s[8][4], o[8][4];
    float m_i[2] = {-1e30f, -1e30f}, l_i[2] = {0.0f, 0.0f};
#pragma unroll
    for (int nt = 0; nt < 8; nt++)
#pragma unroll
        for (int e = 0; e < 4; e++) o[nt][e] = 0.0f;
    uint32_t qfh[4][4], qfl[4][4];

    const int NKT = 2*qt + 2;
    for (int c = 0; c < NKT; c++) {
        cp_wait_all();
        __syncthreads();
        if (c == 0) {
#pragma unroll
            for (int ks = 0; ks < 4; ks++) {
                ldsm4(qfh[ks], sb + AQ_OFF         + swz(w*16 + a_row, ks*32 + a_colb));
                ldsm4(qfl[ks], sb + AQ_OFF + 16384 + swz(w*16 + a_row, ks*32 + a_colb));
            }
        }
        if (c + 1 < NKT) { issue_kv((c + 1) & 1, (c + 1) * 64); cp_commit(); }

        const int key0 = c * 64;
        if (key0 <= rowbase + 15) {          // warp has unmasked work
            const uint32_t pb = sb + (c & 1) * ABUF;

            auto load_k = [&](uint32_t (*dst)[2], uint32_t pbase, int ks) {
#pragma unroll
                for (int ng = 0; ng < 4; ng++) {
                    uint32_t t4[4];
                    ldsm4(t4, pbase + swz(ng*16 + b_row, ks*32 + b_colb));
                    dst[ng*2][0] = t4[0]; dst[ng*2][1] = t4[1];
                    dst[ng*2+1][0] = t4[2]; dst[ng*2+1][1] = t4[3];
                }
            };
            auto load_v = [&](uint32_t (*dst)[2], uint32_t pbase, int ks) {
#pragma unroll
                for (int ng = 0; ng < 4; ng++) {
                    uint32_t t4[4];
                    ldsm4t(t4, pbase + swz(ks*16 + v_row, ng*32 + v_colb));
                    dst[ng*2][0] = t4[0]; dst[ng*2][1] = t4[1];
                    dst[ng*2+1][0] = t4[2]; dst[ng*2+1][1] = t4[3];
                }
            };

            // ---- S = Qh*Kh + Ql*Kh + Qh*Kl (pipelined K fragments) ----
#pragma unroll
            for (int nt = 0; nt < 8; nt++)
#pragma unroll
                for (int e = 0; e < 4; e++) s[nt][e] = 0.0f;
            {
                uint32_t bK[2][8][2], bKl[8][2];
                load_k(bK[0], pb, 0);
#pragma unroll
                for (int ks = 0; ks < 4; ks++) {
                    const int cur = ks & 1;
                    load_k(bKl, pb + AKV, ks);
#pragma unroll
                    for (int nt = 0; nt < 8; nt++) mma_bf16(s[nt], qfh[ks], bK[cur][nt]);
                    if (ks < 3) load_k(bK[cur ^ 1], pb, ks + 1);
#pragma unroll
                    for (int nt = 0; nt < 8; nt++) mma_bf16(s[nt], qfl[ks], bK[cur][nt]);
#pragma unroll
                    for (int nt = 0; nt < 8; nt++) mma_bf16(s[nt], qfh[ks], bKl[nt]);
                }
            }

            // ---- causal mask (diagonal chunks only) ----
            if (key0 + 63 > rowbase) {
#pragma unroll
                for (int nt = 0; nt < 8; nt++) {
#pragma unroll
                    for (int e = 0; e < 4; e++) {
                        int col = key0 + nt*8 + 2*tig + (e & 1);
                        int row = rowbase + g + ((e >= 2) ? 8 : 0);
                        if (col > row) s[nt][e] = -1e30f;
                    }
                }
            }

            // ---- online softmax ----
            float rm0 = -1e30f, rm1 = -1e30f;
#pragma unroll
            for (int nt = 0; nt < 8; nt++) {
                rm0 = fmaxf(rm0, fmaxf(s[nt][0], s[nt][1]));
                rm1 = fmaxf(rm1, fmaxf(s[nt][2], s[nt][3]));
            }
            rm0 = fmaxf(rm0, __shfl_xor_sync(0xffffffffu, rm0, 1));
            rm0 = fmaxf(rm0, __shfl_xor_sync(0xffffffffu, rm0, 2));
            rm1 = fmaxf(rm1, __shfl_xor_sync(0xffffffffu, rm1, 1));
            rm1 = fmaxf(rm1, __shfl_xor_sync(0xffffffffu, rm1, 2));
            float mn0 = fmaxf(m_i[0], rm0), mn1 = fmaxf(m_i[1], rm1);
            float al0 = __expf(m_i[0] - mn0), al1 = __expf(m_i[1] - mn1);
            m_i[0] = mn0; m_i[1] = mn1;
            float rs0 = 0.0f, rs1 = 0.0f;
#pragma unroll
            for (int nt = 0; nt < 8; nt++) {
                s[nt][0] = __expf(s[nt][0] - mn0);
                s[nt][1] = __expf(s[nt][1] - mn0);
                s[nt][2] = __expf(s[nt][2] - mn1);
                s[nt][3] = __expf(s[nt][3] - mn1);
                rs0 += s[nt][0] + s[nt][1];
                rs1 += s[nt][2] + s[nt][3];
            }
            rs0 += __shfl_xor_sync(0xffffffffu, rs0, 1);
            rs0 += __shfl_xor_sync(0xffffffffu, rs0, 2);
            rs1 += __shfl_xor_sync(0xffffffffu, rs1, 1);
            rs1 += __shfl_xor_sync(0xffffffffu, rs1, 2);
            l_i[0] = l_i[0]*al0 + rs0;
            l_i[1] = l_i[1]*al1 + rs1;
#pragma unroll
            for (int nt = 0; nt < 8; nt++) {
                o[nt][0] *= al0; o[nt][1] *= al0;
                o[nt][2] *= al1; o[nt][3] *= al1;
            }

            // ---- O += Ph*Vh + Pl*Vh + Ph*Vl (pipelined V fragments) ----
            {
                uint32_t bV[2][8][2], bVl[8][2];
                load_v(bV[0], pb + 2*AKV, 0);
#pragma unroll
                for (int ks = 0; ks < 4; ks++) {
                    const int cur = ks & 1;
                    uint32_t ph[4], pl[4];
                    split2(s[2*ks][0],   s[2*ks][1],   ph[0], pl[0]);
                    split2(s[2*ks][2],   s[2*ks][3],   ph[1], pl[1]);
                    split2(s[2*ks+1][0], s[2*ks+1][1], ph[2], pl[2]);
                    split2(s[2*ks+1][2], s[2*ks+1][3], ph[3], pl[3]);
                    load_v(bVl, pb + 3*AKV, ks);
#pragma unroll
                    for (int nt = 0; nt < 8; nt++) mma_bf16(o[nt], ph, bV[cur][nt]);
                    if (ks < 3) load_v(bV[cur ^ 1], pb + 2*AKV, ks + 1);
#pragma unroll
                    for (int nt = 0; nt < 8; nt++) mma_bf16(o[nt], pl, bV[cur][nt]);
#pragma unroll
                    for (int nt = 0; nt < 8; nt++) mma_bf16(o[nt], ph, bVl[nt]);
                }
            }
        }
    }

    // ---- epilogue ----
    const int b_ = bh >> 4;
    const int h  = bh & 15;
    const float inv0 = 1.0f / l_i[0];
    const float inv1 = 1.0f / l_i[1];
    const int t0r = rowbase + g;
    const int t1r = rowbase + g + 8;
#pragma unroll
    for (int nt = 0; nt < 8; nt++) {
        const int col = h*64 + nt*8 + 2*tig;
        uint32_t hi, lo;
        split2(o[nt][0]*inv0, o[nt][1]*inv0, hi, lo);
        size_t i0 = ((size_t)(b_*TSEQ) + t0r) * DM + col;
        *(uint32_t*)(ch_g + i0) = hi;
        *(uint32_t*)(cl_g + i0) = lo;
        split2(o[nt][2]*inv1, o[nt][3]*inv1, hi, lo);
        size_t i1 = ((size_t)(b_*TSEQ) + t1r) * DM + col;
        *(uint32_t*)(ch_g + i1) = hi;
        *(uint32_t*)(cl_g + i1) = lo;
    }
}

// ---------------------------------------------------------------------------
extern "C" void kernel_launch(void* const* d_in, const int* in_sizes, int n_in,
                              void* d_out, int out_size)
{
    const float* x  = (const float*)d_in[0];
    const float* Wq = (const float*)d_in[1];
    const float* Wk = (const float*)d_in[2];
    const float* Wv = (const float*)d_in[3];
    const float* Wo = (const float*)d_in[4];
    const float* bo = (const float*)d_in[5];
    float* out = (float*)d_out;

    __nv_bfloat16 *qh, *ql, *kh, *kl, *vh, *vl;
    __nv_bfloat16 *xh, *xl, *wh, *wl, *ch, *cl, *woh, *wol;
    cudaGetSymbolAddress((void**)&qh,  g_qh);
    cudaGetSymbolAddress((void**)&ql,  g_ql);
    cudaGetSymbolAddress((void**)&kh,  g_kh);
    cudaGetSymbolAddress((void**)&kl,  g_kl);
    cudaGetSymbolAddress((void**)&vh,  g_vh);
    cudaGetSymbolAddress((void**)&vl,  g_vl);
    cudaGetSymbolAddress((void**)&xh,  g_xh);
    cudaGetSymbolAddress((void**)&xl,  g_xl);
    cudaGetSymbolAddress((void**)&wh,  g_wh);
    cudaGetSymbolAddress((void**)&wl,  g_wl);
    cudaGetSymbolAddress((void**)&ch,  g_ch);
    cudaGetSymbolAddress((void**)&cl,  g_cl);
    cudaGetSymbolAddress((void**)&woh, g_woh);
    cudaGetSymbolAddress((void**)&wol, g_wol);

    cudaFuncSetAttribute(mma_gemm<0>,
                         cudaFuncAttributeMaxDynamicSharedMemorySize, GEMM_SMEM);
    cudaFuncSetAttribute(mma_gemm<1>,
                         cudaFuncAttributeMaxDynamicSharedMemorySize, GEMM_SMEM);
    cudaFuncSetAttribute(attn_mma,
                         cudaFuncAttributeMaxDynamicSharedMemorySize, ATTN_SMEM);

    // single merged split launch (reference swaps names: q = x@Wk^T, k = x@Wq^T)
    split5_kernel<<<XB + 4*WB, 256>>>(x, Wk, Wq, Wv, Wo,
                                      xh, xl, wh, wl, woh, wol);

    // fused QKV projection (N=3072), bf16 hi/lo epilogue
    mma_gemm<0><<<dim3(3*DM/128, MTOT/128), 256, GEMM_SMEM>>>(
        xh, xl, wh, wl, qh, ql, kh, kl, vh, vl, nullptr, nullptr);

    attn_mma<<<dim3(TSEQ/128, BATCH*NH), 256, ATTN_SMEM>>>(
        qh, ql, kh, kl, vh, vl, ch, cl);

    mma_gemm<1><<<dim3(DM/128, MTOT/128), 256, GEMM_SMEM>>>(
        ch, cl, woh, wol, nullptr, nullptr, nullptr, nullptr, nullptr, nullptr,
        out, bo);
}

// round 10
// speedup vs baseline: 1.5382x; 1.5382x over previous
#include <cuda_runtime.h>
#include <cuda_bf16.h>
#include <math.h>
#include <stdint.h>

#define BATCH 2
#define TSEQ  2048
#define DM    1024
#define NH    16
#define DH    64
#define MTOT  (BATCH*TSEQ)   // 4096

// ---------------- scratch (device globals; no allocation allowed) ----------
__device__ __align__(16) __nv_bfloat16 g_qh[(size_t)BATCH*NH*TSEQ*DH];
__device__ __align__(16) __nv_bfloat16 g_ql[(size_t)BATCH*NH*TSEQ*DH];
__device__ __align__(16) __nv_bfloat16 g_kh[(size_t)BATCH*NH*TSEQ*DH];
__device__ __align__(16) __nv_bfloat16 g_kl[(size_t)BATCH*NH*TSEQ*DH];
__device__ __align__(16) __nv_bfloat16 g_vh[(size_t)BATCH*NH*TSEQ*DH];
__device__ __align__(16) __nv_bfloat16 g_vl[(size_t)BATCH*NH*TSEQ*DH];

__device__ __align__(16) __nv_bfloat16 g_xh[(size_t)MTOT*DM];
__device__ __align__(16) __nv_bfloat16 g_xl[(size_t)MTOT*DM];
__device__ __align__(16) __nv_bfloat16 g_wh[(size_t)3*DM*DM];  // [Wk;Wq;Wv] (q<-Wk swap!)
__device__ __align__(16) __nv_bfloat16 g_wl[(size_t)3*DM*DM];
__device__ __align__(16) __nv_bfloat16 g_ch[(size_t)MTOT*DM];
__device__ __align__(16) __nv_bfloat16 g_cl[(size_t)MTOT*DM];
__device__ __align__(16) __nv_bfloat16 g_woh[(size_t)DM*DM];
__device__ __align__(16) __nv_bfloat16 g_wol[(size_t)DM*DM];

// ---------------- helpers ---------------------------------------------------
__device__ __forceinline__ uint32_t smem_u32(const void* p) {
    uint32_t a;
    asm("{ .reg .u64 t; cvta.to.shared.u64 t, %1; cvt.u32.u64 %0, t; }"
        : "=r"(a) : "l"(p));
    return a;
}
__device__ __forceinline__ void cp_async16(uint32_t dst, const void* src) {
    asm volatile("cp.async.cg.shared.global [%0], [%1], 16;"
                 :: "r"(dst), "l"(src) : "memory");
}
__device__ __forceinline__ void cp_commit() {
    asm volatile("cp.async.commit_group;" ::: "memory");
}
__device__ __forceinline__ void cp_wait_all() {
    asm volatile("cp.async.wait_group 0;" ::: "memory");
}
__device__ __forceinline__ void ldsm4(uint32_t* r, uint32_t a) {
    asm volatile("ldmatrix.sync.aligned.m8n8.x4.shared.b16 {%0,%1,%2,%3}, [%4];"
                 : "=r"(r[0]), "=r"(r[1]), "=r"(r[2]), "=r"(r[3]) : "r"(a));
}
__device__ __forceinline__ void ldsm4t(uint32_t* r, uint32_t a) {
    asm volatile("ldmatrix.sync.aligned.m8n8.x4.trans.shared.b16 {%0,%1,%2,%3}, [%4];"
                 : "=r"(r[0]), "=r"(r[1]), "=r"(r[2]), "=r"(r[3]) : "r"(a));
}
__device__ __forceinline__ void mma_bf16(float* c, const uint32_t* a, const uint32_t* b) {
    asm volatile(
        "mma.sync.aligned.m16n8k16.row.col.f32.bf16.bf16.f32 "
        "{%0,%1,%2,%3}, {%4,%5,%6,%7}, {%8,%9}, {%0,%1,%2,%3};"
        : "+f"(c[0]), "+f"(c[1]), "+f"(c[2]), "+f"(c[3])
        : "r"(a[0]), "r"(a[1]), "r"(a[2]), "r"(a[3]), "r"(b[0]), "r"(b[1]));
}
__device__ __forceinline__ uint32_t cvt2(float v_hi, float v_lo) {
    uint32_t r;
    asm("cvt.rn.bf16x2.f32 %0, %1, %2;" : "=r"(r) : "f"(v_hi), "f"(v_lo));
    return r;
}
__device__ __forceinline__ void split2(float v0, float v1, uint32_t& hi, uint32_t& lo) {
    hi = cvt2(v1, v0);
    float h0 = __uint_as_float(hi << 16);
    float h1 = __uint_as_float(hi & 0xffff0000u);
    lo = cvt2(v1 - h1, v0 - h0);
}
__device__ __forceinline__ uint32_t swz(int row, int colb) {
    uint32_t off = row * 128 + colb;
    return off ^ ((off >> 3) & 0x70);
}

// ---------------- merged fp32 -> bf16 hi/lo split (5 segments) --------------
#define XB ((MTOT*DM/4)/256)     // 4096 blocks
#define WB ((DM*DM/4)/256)       // 1024 blocks

__global__ void __launch_bounds__(256) split5_kernel(
    const float* __restrict__ x,  const float* __restrict__ Wk,
    const float* __restrict__ Wq, const float* __restrict__ Wv,
    const float* __restrict__ Wo,
    __nv_bfloat16* __restrict__ xh, __nv_bfloat16* __restrict__ xl,
    __nv_bfloat16* __restrict__ wh, __nv_bfloat16* __restrict__ wl,
    __nv_bfloat16* __restrict__ woh, __nv_bfloat16* __restrict__ wol)
{
    int blk = blockIdx.x;
    const float* src;
    __nv_bfloat16 *dh, *dl;
    int i;
    if (blk < XB) {
        src = x; dh = xh; dl = xl;
        i = blk * 256 + threadIdx.x;
    } else {
        int wseg = (blk - XB) / WB;        // 0..3
        int wblk = (blk - XB) % WB;
        i = wblk * 256 + threadIdx.x;
        if (wseg == 0)      { src = Wk; dh = wh;            dl = wl; }
        else if (wseg == 1) { src = Wq; dh = wh + DM*DM;    dl = wl + DM*DM; }
        else if (wseg == 2) { src = Wv; dh = wh + 2*DM*DM;  dl = wl + 2*DM*DM; }
        else                { src = Wo; dh = woh;           dl = wol; }
    }
    float4 v = ((const float4*)src)[i];
    __nv_bfloat16 h[4], l[4];
    float f[4] = {v.x, v.y, v.z, v.w};
#pragma unroll
    for (int j = 0; j < 4; j++) {
        h[j] = __float2bfloat16(f[j]);
        l[j] = __float2bfloat16(f[j] - __bfloat162float(h[j]));
    }
    *(uint2*)(dh + (size_t)i*4) = *(uint2*)h;
    *(uint2*)(dl + (size_t)i*4) = *(uint2*)l;
}

// ---------------------------------------------------------------------------
// Split-bf16 GEMM on HMMA. MODE 0: fused QKV -> bf16 hi/lo head-major
// (softmax scale folded into q). MODE 1: fp32 out + bias.
// Round-10 change vs round-6: bL (B-lo) fragment load hoisted before the hh
// MMA burst -> single ldsm->mma join per ks-iter, register-neutral.
// ---------------------------------------------------------------------------
#define GK       DM
#define BK       64
#define NCHUNK   (GK/BK)
#define TILE_B   (128*128)
#define BUF_B    (4*TILE_B)
#define GEMM_SMEM (2*BUF_B)     // 131072

template<int MODE>
__global__ void __launch_bounds__(256, 1) mma_gemm(
    const __nv_bfloat16* __restrict__ Ah, const __nv_bfloat16* __restrict__ Al,
    const __nv_bfloat16* __restrict__ Bh, const __nv_bfloat16* __restrict__ Bl,
    __nv_bfloat16* __restrict__ qh, __nv_bfloat16* __restrict__ ql,
    __nv_bfloat16* __restrict__ kh, __nv_bfloat16* __restrict__ kl,
    __nv_bfloat16* __restrict__ vh, __nv_bfloat16* __restrict__ vl,
    float* __restrict__ out, const float* __restrict__ bias)
{
    extern __shared__ char smem[];
    const uint32_t sb = smem_u32(smem);
    const int tid  = threadIdx.x;
    const int lane = tid & 31;
    const int w    = tid >> 5;
    const int m0   = blockIdx.y * 128;
    const int n0   = blockIdx.x * 128;

    const __nv_bfloat16* srcs[4] = {Ah + (size_t)m0*GK, Al + (size_t)m0*GK,
                                    Bh + (size_t)n0*GK, Bl + (size_t)n0*GK};

    auto issue_chunk = [&](int buf, int k0) {
        uint32_t dbase = sb + buf * BUF_B;
#pragma unroll
        for (int t = 0; t < 4; t++) {
            const __nv_bfloat16* src = srcs[t] + k0;
            uint32_t tb = dbase + t * TILE_B;
#pragma unroll
            for (int r2 = 0; r2 < 4; r2++) {
                int id  = tid + 256 * r2;
                int row = id >> 3;
                int c16 = id & 7;
                cp_async16(tb + swz(row, c16 * 16), src + (size_t)row*GK + c16*8);
            }
        }
        cp_commit();
    };

    float acc[2][8][4];
#pragma unroll
    for (int mt = 0; mt < 2; mt++)
#pragma unroll
        for (int nt = 0; nt < 8; nt++)
#pragma unroll
            for (int e = 0; e < 4; e++) acc[mt][nt][e] = 0.0f;

    const int mr  = (w & 3) * 32;
    const int nc0 = (w >> 2) * 64;
    const int quad = lane >> 3;
    const int l7   = lane & 7;
    const int a_row_off = (quad & 1) * 8 + l7;
    const int a_col_off = (quad >> 1) * 16;
    const int b_row_off = (quad >> 1) * 8 + l7;
    const int b_col_off = (quad & 1) * 16;

    issue_chunk(0, 0);

    for (int c = 0; c < NCHUNK; c++) {
        const int b = c & 1;
        cp_wait_all();
        __syncthreads();
        if (c + 1 < NCHUNK) issue_chunk(b ^ 1, (c + 1) * BK);

        const uint32_t pAh = sb + b*BUF_B;
        const uint32_t pAl = pAh + TILE_B;
        const uint32_t pBh = pAh + 2*TILE_B;
        const uint32_t pBl = pAh + 3*TILE_B;

#pragma unroll
        for (int ks = 0; ks < 4; ks++) {
            const int k0b = ks * 32;
            uint32_t aH[2][4], aL[2][4], bF[8][2], bL[8][2];
#pragma unroll
            for (int mt = 0; mt < 2; mt++) {
                int row = mr + mt*16 + a_row_off;
                ldsm4(aH[mt], pAh + swz(row, k0b + a_col_off));
                ldsm4(aL[mt], pAl + swz(row, k0b + a_col_off));
            }
#pragma unroll
            for (int ng = 0; ng < 4; ng++) {
                uint32_t t4[4];
                ldsm4(t4, pBh + swz(nc0 + ng*16 + b_row_off, k0b + b_col_off));
                bF[ng*2][0] = t4[0]; bF[ng*2][1] = t4[1];
                bF[ng*2+1][0] = t4[2]; bF[ng*2+1][1] = t4[3];
            }
            // hoisted: B-lo fragments loaded before the MMA bursts
#pragma unroll
            for (int ng = 0; ng < 4; ng++) {
                uint32_t t4[4];
                ldsm4(t4, pBl + swz(nc0 + ng*16 + b_row_off, k0b + b_col_off));
                bL[ng*2][0] = t4[0]; bL[ng*2][1] = t4[1];
                bL[ng*2+1][0] = t4[2]; bL[ng*2+1][1] = t4[3];
            }
            // hh
#pragma unroll
            for (int mt = 0; mt < 2; mt++)
#pragma unroll
                for (int nt = 0; nt < 8; nt++) mma_bf16(acc[mt][nt], aH[mt], bF[nt]);
            // lh
#pragma unroll
            for (int mt = 0; mt < 2; mt++)
#pragma unroll
                for (int nt = 0; nt < 8; nt++) mma_bf16(acc[mt][nt], aL[mt], bF[nt]);
            // hl
#pragma unroll
            for (int mt = 0; mt < 2; mt++)
#pragma unroll
                for (int nt = 0; nt < 8; nt++) mma_bf16(acc[mt][nt], aH[mt], bL[nt]);
        }
        __syncthreads();
    }

    // ---- epilogue ----
#pragma unroll
    for (int mt = 0; mt < 2; mt++) {
#pragma unroll
        for (int half = 0; half < 2; half++) {
            const int m = m0 + mr + mt*16 + (lane >> 2) + half*8;
#pragma unroll
            for (int nt = 0; nt < 8; nt++) {
                const int n = n0 + nc0 + nt*8 + (lane & 3)*2;
                const float c0 = acc[mt][nt][half*2 + 0];
                const float c1 = acc[mt][nt][half*2 + 1];
                if (MODE == 0) {
                    const int bb  = m >> 11;
                    const int t   = m & 2047;
                    const int mat = n >> 10;
                    const int np  = n & 1023;
                    const float sc = (mat == 0) ? 0.125f : 1.0f;
                    uint32_t hi, lo;
                    split2(c0*sc, c1*sc, hi, lo);
                    __nv_bfloat16* ph = (mat == 0) ? qh : ((mat == 1) ? kh : vh);
                    __nv_bfloat16* pl = (mat == 0) ? ql : ((mat == 1) ? kl : vl);
                    size_t idx = ((size_t)(bb*NH + (np >> 6)) * TSEQ + t) * DH + (np & 63);
                    *(uint32_t*)(ph + idx) = hi;
                    *(uint32_t*)(pl + idx) = lo;
                } else {
                    float* p = out + (size_t)m * DM + n;
                    p[0] = c0 + __ldg(bias + n);
                    p[1] = c1 + __ldg(bias + n + 1);
                }
            }
        }
    }
}

// ---------------------------------------------------------------------------
// Causal flash attention on HMMA, split-bf16 — byte-identical to round 6
// (register-saturated; do not extend fragment live ranges here).
// ---------------------------------------------------------------------------
#define AKV   8192
#define ABUF  (4*AKV)
#define AQ_OFF (2*ABUF)
#define ATTN_SMEM (2*ABUF + 2*16384)   // 98304

__global__ void __launch_bounds__(256, 1) attn_mma(
    const __nv_bfloat16* __restrict__ qh_g, const __nv_bfloat16* __restrict__ ql_g,
    const __nv_bfloat16* __restrict__ kh_g, const __nv_bfloat16* __restrict__ kl_g,
    const __nv_bfloat16* __restrict__ vh_g, const __nv_bfloat16* __restrict__ vl_g,
    __nv_bfloat16* __restrict__ ch_g, __nv_bfloat16* __restrict__ cl_g)
{
    extern __shared__ char smem[];
    const uint32_t sb = smem_u32(smem);
    const int tid  = threadIdx.x;
    const int lane = tid & 31;
    const int w    = tid >> 5;
    const int qt   = (TSEQ/128 - 1) - blockIdx.x;   // longest blocks first
    const int bh   = blockIdx.y;
    const int g    = lane >> 2;
    const int tig  = lane & 3;
    const int quad = lane >> 3;
    const int l7   = lane & 7;
    const int a_row  = (quad & 1) * 8 + l7;
    const int a_colb = (quad >> 1) * 16;
    const int b_row  = (quad >> 1) * 8 + l7;
    const int b_colb = (quad & 1) * 16;
    const int v_row  = (quad & 1) * 8 + l7;
    const int v_colb = (quad >> 1) * 16;

    const size_t base = (size_t)bh * TSEQ * DH;
    const int rowbase = qt * 128 + w * 16;

    auto issue_kv = [&](int buf, int key0) {
        uint32_t db = sb + buf * ABUF;
        const __nv_bfloat16* srcs[4] = {kh_g, kl_g, vh_g, vl_g};
#pragma unroll
        for (int t4 = 0; t4 < 4; t4++) {
#pragma unroll
            for (int r = 0; r < 2; r++) {
                int id  = tid + 256 * r;
                int row = id >> 3;
                int c16 = id & 7;
                cp_async16(db + t4*AKV + swz(row, c16*16),
                           srcs[t4] + base + (size_t)(key0 + row)*DH + c16*8);
            }
        }
    };

#pragma unroll
    for (int r = 0; r < 4; r++) {
        int id  = tid + 256 * r;
        int row = id >> 3;
        int c16 = id & 7;
        cp_async16(sb + AQ_OFF         + swz(row, c16*16),
                   qh_g + base + (size_t)(qt*128 + row)*DH + c16*8);
        cp_async16(sb + AQ_OFF + 16384 + swz(row, c16*16),
                   ql_g + base + (size_t)(qt*128 + row)*DH + c16*8);
    }
    issue_kv(0, 0);
    cp_commit();

    float s[8][4], o[8][4];
    float m_i[2] = {-1e30f, -1e30f}, l_i[2] = {0.0f, 0.0f};
#pragma unroll
    for (int nt = 0; nt < 8; nt++)
#pragma unroll
        for (int e = 0; e < 4; e++) o[nt][e] = 0.0f;
    uint32_t qfh[4][4], qfl[4][4];

    const int NKT = 2*qt + 2;
    for (int c = 0; c < NKT; c++) {
        cp_wait_all();
        __syncthreads();
        if (c == 0) {
#pragma unroll
            for (int ks = 0; ks < 4; ks++) {
                ldsm4(qfh[ks], sb + AQ_OFF         + swz(w*16 + a_row, ks*32 + a_colb));
                ldsm4(qfl[ks], sb + AQ_OFF + 16384 + swz(w*16 + a_row, ks*32 + a_colb));
            }
        }
        if (c + 1 < NKT) { issue_kv((c + 1) & 1, (c + 1) * 64); cp_commit(); }

        const int key0 = c * 64;
        if (key0 <= rowbase + 15) {          // warp has unmasked work
            const uint32_t pb = sb + (c & 1) * ABUF;

            // ---- S = Qh*Kh + Ql*Kh + Qh*Kl ----
#pragma unroll
            for (int nt = 0; nt < 8; nt++)
#pragma unroll
                for (int e = 0; e < 4; e++) s[nt][e] = 0.0f;
#pragma unroll
            for (int ks = 0; ks < 4; ks++) {
                uint32_t bK[8][2], t4[4];
#pragma unroll
                for (int ng = 0; ng < 4; ng++) {
                    ldsm4(t4, pb + swz(ng*16 + b_row, ks*32 + b_colb));   // Kh
                    bK[ng*2][0] = t4[0]; bK[ng*2][1] = t4[1];
                    bK[ng*2+1][0] = t4[2]; bK[ng*2+1][1] = t4[3];
                }
#pragma unroll
                for (int nt = 0; nt < 8; nt++) mma_bf16(s[nt], qfh[ks], bK[nt]);
#pragma unroll
                for (int nt = 0; nt < 8; nt++) mma_bf16(s[nt], qfl[ks], bK[nt]);
#pragma unroll
                for (int ng = 0; ng < 4; ng++) {
                    ldsm4(t4, pb + AKV + swz(ng*16 + b_row, ks*32 + b_colb)); // Kl
                    bK[ng*2][0] = t4[0]; bK[ng*2][1] = t4[1];
                    bK[ng*2+1][0] = t4[2]; bK[ng*2+1][1] = t4[3];
                }
#pragma unroll
                for (int nt = 0; nt < 8; nt++) mma_bf16(s[nt], qfh[ks], bK[nt]);
            }

            // ---- causal mask (diagonal chunks only) ----
            if (key0 + 63 > rowbase) {
#pragma unroll
                for (int nt = 0; nt < 8; nt++) {
#pragma unroll
                    for (int e = 0; e < 4; e++) {
                        int col = key0 + nt*8 + 2*tig + (e & 1);
                        int row = rowbase + g + ((e >= 2) ? 8 : 0);
                        if (col > row) s[nt][e] = -1e30f;
                    }
                }
            }

            // ---- online softmax ----
            float rm0 = -1e30f, rm1 = -1e30f;
#pragma unroll
            for (int nt = 0; nt < 8; nt++) {
                rm0 = fmaxf(rm0, fmaxf(s[nt][0], s[nt][1]));
                rm1 = fmaxf(rm1, fmaxf(s[nt][2], s[nt][3]));
            }
            rm0 = fmaxf(rm0, __shfl_xor_sync(0xffffffffu, rm0, 1));
            rm0 = fmaxf(rm0, __shfl_xor_sync(0xffffffffu, rm0, 2));
            rm1 = fmaxf(rm1, __shfl_xor_sync(0xffffffffu, rm1, 1));
            rm1 = fmaxf(rm1, __shfl_xor_sync(0xffffffffu, rm1, 2));
            float mn0 = fmaxf(m_i[0], rm0), mn1 = fmaxf(m_i[1], rm1);
            float al0 = __expf(m_i[0] - mn0), al1 = __expf(m_i[1] - mn1);
            m_i[0] = mn0; m_i[1] = mn1;
            float rs0 = 0.0f, rs1 = 0.0f;
#pragma unroll
            for (int nt = 0; nt < 8; nt++) {
                s[nt][0] = __expf(s[nt][0] - mn0);
                s[nt][1] = __expf(s[nt][1] - mn0);
                s[nt][2] = __expf(s[nt][2] - mn1);
                s[nt][3] = __expf(s[nt][3] - mn1);
                rs0 += s[nt][0] + s[nt][1];
                rs1 += s[nt][2] + s[nt][3];
            }
            rs0 += __shfl_xor_sync(0xffffffffu, rs0, 1);
            rs0 += __shfl_xor_sync(0xffffffffu, rs0, 2);
            rs1 += __shfl_xor_sync(0xffffffffu, rs1, 1);
            rs1 += __shfl_xor_sync(0xffffffffu, rs1, 2);
            l_i[0] = l_i[0]*al0 + rs0;
            l_i[1] = l_i[1]*al1 + rs1;
#pragma unroll
            for (int nt = 0; nt < 8; nt++) {
                o[nt][0] *= al0; o[nt][1] *= al0;
                o[nt][2] *= al1; o[nt][3] *= al1;
            }

            // ---- O += Ph*Vh + Pl*Vh + Ph*Vl ----
#pragma unroll
            for (int ks = 0; ks < 4; ks++) {
                uint32_t ph[4], pl[4];
                split2(s[2*ks][0],   s[2*ks][1],   ph[0], pl[0]);
                split2(s[2*ks][2],   s[2*ks][3],   ph[1], pl[1]);
                split2(s[2*ks+1][0], s[2*ks+1][1], ph[2], pl[2]);
                split2(s[2*ks+1][2], s[2*ks+1][3], ph[3], pl[3]);
                uint32_t bV[8][2], t4[4];
#pragma unroll
                for (int ng = 0; ng < 4; ng++) {
                    ldsm4t(t4, pb + 2*AKV + swz(ks*16 + v_row, ng*32 + v_colb)); // Vh
                    bV[ng*2][0] = t4[0]; bV[ng*2][1] = t4[1];
                    bV[ng*2+1][0] = t4[2]; bV[ng*2+1][1] = t4[3];
                }
#pragma unroll
                for (int nt = 0; nt < 8; nt++) mma_bf16(o[nt], ph, bV[nt]);
#pragma unroll
                for (int nt = 0; nt < 8; nt++) mma_bf16(o[nt], pl, bV[nt]);
#pragma unroll
                for (int ng = 0; ng < 4; ng++) {
                    ldsm4t(t4, pb + 3*AKV + swz(ks*16 + v_row, ng*32 + v_colb)); // Vl
                    bV[ng*2][0] = t4[0]; bV[ng*2][1] = t4[1];
                    bV[ng*2+1][0] = t4[2]; bV[ng*2+1][1] = t4[3];
                }
#pragma unroll
                for (int nt = 0; nt < 8; nt++) mma_bf16(o[nt], ph, bV[nt]);
            }
        }
    }

    // ---- epilogue ----
    const int b_ = bh >> 4;
    const int h  = bh & 15;
    const float inv0 = 1.0f / l_i[0];
    const float inv1 = 1.0f / l_i[1];
    const int t0r = rowbase + g;
    const int t1r = rowbase + g + 8;
#pragma unroll
    for (int nt = 0; nt < 8; nt++) {
        const int col = h*64 + nt*8 + 2*tig;
        uint32_t hi, lo;
        split2(o[nt][0]*inv0, o[nt][1]*inv0, hi, lo);
        size_t i0 = ((size_t)(b_*TSEQ) + t0r) * DM + col;
        *(uint32_t*)(ch_g + i0) = hi;
        *(uint32_t*)(cl_g + i0) = lo;
        split2(o[nt][2]*inv1, o[nt][3]*inv1, hi, lo);
        size_t i1 = ((size_t)(b_*TSEQ) + t1r) * DM + col;
        *(uint32_t*)(ch_g + i1) = hi;
        *(uint32_t*)(cl_g + i1) = lo;
    }
}

// ---------------------------------------------------------------------------
extern "C" void kernel_launch(void* const* d_in, const int* in_sizes, int n_in,
                              void* d_out, int out_size)
{
    const float* x  = (const float*)d_in[0];
    const float* Wq = (const float*)d_in[1];
    const float* Wk = (const float*)d_in[2];
    const float* Wv = (const float*)d_in[3];
    const float* Wo = (const float*)d_in[4];
    const float* bo = (const float*)d_in[5];
    float* out = (float*)d_out;

    __nv_bfloat16 *qh, *ql, *kh, *kl, *vh, *vl;
    __nv_bfloat16 *xh, *xl, *wh, *wl, *ch, *cl, *woh, *wol;
    cudaGetSymbolAddress((void**)&qh,  g_qh);
    cudaGetSymbolAddress((void**)&ql,  g_ql);
    cudaGetSymbolAddress((void**)&kh,  g_kh);
    cudaGetSymbolAddress((void**)&kl,  g_kl);
    cudaGetSymbolAddress((void**)&vh,  g_vh);
    cudaGetSymbolAddress((void**)&vl,  g_vl);
    cudaGetSymbolAddress((void**)&xh,  g_xh);
    cudaGetSymbolAddress((void**)&xl,  g_xl);
    cudaGetSymbolAddress((void**)&wh,  g_wh);
    cudaGetSymbolAddress((void**)&wl,  g_wl);
    cudaGetSymbolAddress((void**)&ch,  g_ch);
    cudaGetSymbolAddress((void**)&cl,  g_cl);
    cudaGetSymbolAddress((void**)&woh, g_woh);
    cudaGetSymbolAddress((void**)&wol, g_wol);

    cudaFuncSetAttribute(mma_gemm<0>,
                         cudaFuncAttributeMaxDynamicSharedMemorySize, GEMM_SMEM);
    cudaFuncSetAttribute(mma_gemm<1>,
                         cudaFuncAttributeMaxDynamicSharedMemorySize, GEMM_SMEM);
    cudaFuncSetAttribute(attn_mma,
                         cudaFuncAttributeMaxDynamicSharedMemorySize, ATTN_SMEM);

    // single merged split launch (reference swaps names: q = x@Wk^T, k = x@Wq^T)
    split5_kernel<<<XB + 4*WB, 256>>>(x, Wk, Wq, Wv, Wo,
                                      xh, xl, wh, wl, woh, wol);

    // fused QKV projection (N=3072), bf16 hi/lo epilogue
    mma_gemm<0><<<dim3(3*DM/128, MTOT/128), 256, GEMM_SMEM>>>(
        xh, xl, wh, wl, qh, ql, kh, kl, vh, vl, nullptr, nullptr);

    attn_mma<<<dim3(TSEQ/128, BATCH*NH), 256, ATTN_SMEM>>>(
        qh, ql, kh, kl, vh, vl, ch, cl);

    mma_gemm<1><<<dim3(DM/128, MTOT/128), 256, GEMM_SMEM>>>(
        ch, cl, woh, wol, nullptr, nullptr, nullptr, nullptr, nullptr, nullptr,
        out, bo);
}

// round 11
// speedup vs baseline: 1.5448x; 1.0043x over previous
#include <cuda_runtime.h>
#include <cuda_bf16.h>
#include <math.h>
#include <stdint.h>

#define BATCH 2
#define TSEQ  2048
#define DM    1024
#define NH    16
#define DH    64
#define MTOT  (BATCH*TSEQ)   // 4096

// ---------------- scratch (device globals; no allocation allowed) ----------
__device__ __align__(16) __nv_bfloat16 g_qh[(size_t)BATCH*NH*TSEQ*DH];
__device__ __align__(16) __nv_bfloat16 g_ql[(size_t)BATCH*NH*TSEQ*DH];
__device__ __align__(16) __nv_bfloat16 g_kh[(size_t)BATCH*NH*TSEQ*DH];
__device__ __align__(16) __nv_bfloat16 g_kl[(size_t)BATCH*NH*TSEQ*DH];
__device__ __align__(16) __nv_bfloat16 g_vh[(size_t)BATCH*NH*TSEQ*DH];
__device__ __align__(16) __nv_bfloat16 g_vl[(size_t)BATCH*NH*TSEQ*DH];

__device__ __align__(16) __nv_bfloat16 g_xh[(size_t)MTOT*DM];
__device__ __align__(16) __nv_bfloat16 g_xl[(size_t)MTOT*DM];
__device__ __align__(16) __nv_bfloat16 g_wh[(size_t)3*DM*DM];  // [Wk;Wq;Wv] (q<-Wk swap!)
__device__ __align__(16) __nv_bfloat16 g_wl[(size_t)3*DM*DM];
__device__ __align__(16) __nv_bfloat16 g_ch[(size_t)MTOT*DM];
__device__ __align__(16) __nv_bfloat16 g_cl[(size_t)MTOT*DM];
__device__ __align__(16) __nv_bfloat16 g_woh[(size_t)DM*DM];
__device__ __align__(16) __nv_bfloat16 g_wol[(size_t)DM*DM];

// ---------------- helpers ---------------------------------------------------
__device__ __forceinline__ uint32_t smem_u32(const void* p) {
    uint32_t a;
    asm("{ .reg .u64 t; cvta.to.shared.u64 t, %1; cvt.u32.u64 %0, t; }"
        : "=r"(a) : "l"(p));
    return a;
}
__device__ __forceinline__ void cp_async16(uint32_t dst, const void* src) {
    asm volatile("cp.async.cg.shared.global [%0], [%1], 16;"
                 :: "r"(dst), "l"(src) : "memory");
}
__device__ __forceinline__ void cp_commit() {
    asm volatile("cp.async.commit_group;" ::: "memory");
}
__device__ __forceinline__ void cp_wait_all() {
    asm volatile("cp.async.wait_group 0;" ::: "memory");
}
__device__ __forceinline__ void cp_wait_1() {
    asm volatile("cp.async.wait_group 1;" ::: "memory");
}
__device__ __forceinline__ void ldsm4(uint32_t* r, uint32_t a) {
    asm volatile("ldmatrix.sync.aligned.m8n8.x4.shared.b16 {%0,%1,%2,%3}, [%4];"
                 : "=r"(r[0]), "=r"(r[1]), "=r"(r[2]), "=r"(r[3]) : "r"(a));
}
__device__ __forceinline__ void ldsm4t(uint32_t* r, uint32_t a) {
    asm volatile("ldmatrix.sync.aligned.m8n8.x4.trans.shared.b16 {%0,%1,%2,%3}, [%4];"
                 : "=r"(r[0]), "=r"(r[1]), "=r"(r[2]), "=r"(r[3]) : "r"(a));
}
__device__ __forceinline__ void mma_bf16(float* c, const uint32_t* a, const uint32_t* b) {
    asm volatile(
        "mma.sync.aligned.m16n8k16.row.col.f32.bf16.bf16.f32 "
        "{%0,%1,%2,%3}, {%4,%5,%6,%7}, {%8,%9}, {%0,%1,%2,%3};"
        : "+f"(c[0]), "+f"(c[1]), "+f"(c[2]), "+f"(c[3])
        : "r"(a[0]), "r"(a[1]), "r"(a[2]), "r"(a[3]), "r"(b[0]), "r"(b[1]));
}
__device__ __forceinline__ uint32_t cvt2(float v_hi, float v_lo) {
    uint32_t r;
    asm("cvt.rn.bf16x2.f32 %0, %1, %2;" : "=r"(r) : "f"(v_hi), "f"(v_lo));
    return r;
}
__device__ __forceinline__ void split2(float v0, float v1, uint32_t& hi, uint32_t& lo) {
    hi = cvt2(v1, v0);
    float h0 = __uint_as_float(hi << 16);
    float h1 = __uint_as_float(hi & 0xffff0000u);
    lo = cvt2(v1 - h1, v0 - h0);
}
__device__ __forceinline__ uint32_t swz(int row, int colb) {
    uint32_t off = row * 128 + colb;
    return off ^ ((off >> 3) & 0x70);
}

// ---------------- merged fp32 -> bf16 hi/lo split (5 segments) --------------
#define XB ((MTOT*DM/4)/256)     // 4096 blocks
#define WB ((DM*DM/4)/256)       // 1024 blocks

__global__ void __launch_bounds__(256) split5_kernel(
    const float* __restrict__ x,  const float* __restrict__ Wk,
    const float* __restrict__ Wq, const float* __restrict__ Wv,
    const float* __restrict__ Wo,
    __nv_bfloat16* __restrict__ xh, __nv_bfloat16* __restrict__ xl,
    __nv_bfloat16* __restrict__ wh, __nv_bfloat16* __restrict__ wl,
    __nv_bfloat16* __restrict__ woh, __nv_bfloat16* __restrict__ wol)
{
    int blk = blockIdx.x;
    const float* src;
    __nv_bfloat16 *dh, *dl;
    int i;
    if (blk < XB) {
        src = x; dh = xh; dl = xl;
        i = blk * 256 + threadIdx.x;
    } else {
        int wseg = (blk - XB) / WB;        // 0..3
        int wblk = (blk - XB) % WB;
        i = wblk * 256 + threadIdx.x;
        if (wseg == 0)      { src = Wk; dh = wh;            dl = wl; }
        else if (wseg == 1) { src = Wq; dh = wh + DM*DM;    dl = wl + DM*DM; }
        else if (wseg == 2) { src = Wv; dh = wh + 2*DM*DM;  dl = wl + 2*DM*DM; }
        else                { src = Wo; dh = woh;           dl = wol; }
    }
    float4 v = ((const float4*)src)[i];
    __nv_bfloat16 h[4], l[4];
    float f[4] = {v.x, v.y, v.z, v.w};
#pragma unroll
    for (int j = 0; j < 4; j++) {
        h[j] = __float2bfloat16(f[j]);
        l[j] = __float2bfloat16(f[j] - __bfloat162float(h[j]));
    }
    *(uint2*)(dh + (size_t)i*4) = *(uint2*)h;
    *(uint2*)(dl + (size_t)i*4) = *(uint2*)l;
}

// ---------------------------------------------------------------------------
// Split-bf16 GEMM on HMMA, 3-stage cp.async pipeline (prefetch depth 2,
// wait_group 1) — latency of each chunk's loads is covered by a FULL chunk
// of compute. One barrier per chunk. Register-neutral vs round 10.
// MODE 0: fused QKV -> bf16 hi/lo head-major (scale folded into q).
// MODE 1: fp32 out + bias.
// ---------------------------------------------------------------------------
#define GK       DM
#define BK       64
#define NCHUNK   (GK/BK)        // 16
#define TILE_B   (128*128)
#define BUF_B    (4*TILE_B)     // 64 KB
#define GEMM_SMEM (3*BUF_B)     // 196608

template<int MODE>
__global__ void __launch_bounds__(256, 1) mma_gemm(
    const __nv_bfloat16* __restrict__ Ah, const __nv_bfloat16* __restrict__ Al,
    const __nv_bfloat16* __restrict__ Bh, const __nv_bfloat16* __restrict__ Bl,
    __nv_bfloat16* __restrict__ qh, __nv_bfloat16* __restrict__ ql,
    __nv_bfloat16* __restrict__ kh, __nv_bfloat16* __restrict__ kl,
    __nv_bfloat16* __restrict__ vh, __nv_bfloat16* __restrict__ vl,
    float* __restrict__ out, const float* __restrict__ bias)
{
    extern __shared__ char smem[];
    const uint32_t sb = smem_u32(smem);
    const int tid  = threadIdx.x;
    const int lane = tid & 31;
    const int w    = tid >> 5;
    const int m0   = blockIdx.y * 128;
    const int n0   = blockIdx.x * 128;

    const __nv_bfloat16* srcs[4] = {Ah + (size_t)m0*GK, Al + (size_t)m0*GK,
                                    Bh + (size_t)n0*GK, Bl + (size_t)n0*GK};

    auto issue_chunk = [&](int buf, int k0) {
        uint32_t dbase = sb + buf * BUF_B;
#pragma unroll
        for (int t = 0; t < 4; t++) {
            const __nv_bfloat16* src = srcs[t] + k0;
            uint32_t tb = dbase + t * TILE_B;
#pragma unroll
            for (int r2 = 0; r2 < 4; r2++) {
                int id  = tid + 256 * r2;
                int row = id >> 3;
                int c16 = id & 7;
                cp_async16(tb + swz(row, c16 * 16), src + (size_t)row*GK + c16*8);
            }
        }
        cp_commit();
    };

    float acc[2][8][4];
#pragma unroll
    for (int mt = 0; mt < 2; mt++)
#pragma unroll
        for (int nt = 0; nt < 8; nt++)
#pragma unroll
            for (int e = 0; e < 4; e++) acc[mt][nt][e] = 0.0f;

    const int mr  = (w & 3) * 32;
    const int nc0 = (w >> 2) * 64;
    const int quad = lane >> 3;
    const int l7   = lane & 7;
    const int a_row_off = (quad & 1) * 8 + l7;
    const int a_col_off = (quad >> 1) * 16;
    const int b_row_off = (quad >> 1) * 8 + l7;
    const int b_col_off = (quad & 1) * 16;

    issue_chunk(0, 0);
    issue_chunk(1, BK);

    for (int c = 0; c < NCHUNK; c++) {
        if (c + 1 < NCHUNK) cp_wait_1(); else cp_wait_all();
        __syncthreads();
        if (c + 2 < NCHUNK) issue_chunk((c + 2) % 3, (c + 2) * BK);

        const uint32_t pAh = sb + (c % 3) * BUF_B;
        const uint32_t pAl = pAh + TILE_B;
        const uint32_t pBh = pAh + 2*TILE_B;
        const uint32_t pBl = pAh + 3*TILE_B;

#pragma unroll
        for (int ks = 0; ks < 4; ks++) {
            const int k0b = ks * 32;
            uint32_t aH[2][4], aL[2][4], bF[8][2], bL[8][2];
#pragma unroll
            for (int mt = 0; mt < 2; mt++) {
                int row = mr + mt*16 + a_row_off;
                ldsm4(aH[mt], pAh + swz(row, k0b + a_col_off));
                ldsm4(aL[mt], pAl + swz(row, k0b + a_col_off));
            }
#pragma unroll
            for (int ng = 0; ng < 4; ng++) {
                uint32_t t4[4];
                ldsm4(t4, pBh + swz(nc0 + ng*16 + b_row_off, k0b + b_col_off));
                bF[ng*2][0] = t4[0]; bF[ng*2][1] = t4[1];
                bF[ng*2+1][0] = t4[2]; bF[ng*2+1][1] = t4[3];
            }
#pragma unroll
            for (int ng = 0; ng < 4; ng++) {
                uint32_t t4[4];
                ldsm4(t4, pBl + swz(nc0 + ng*16 + b_row_off, k0b + b_col_off));
                bL[ng*2][0] = t4[0]; bL[ng*2][1] = t4[1];
                bL[ng*2+1][0] = t4[2]; bL[ng*2+1][1] = t4[3];
            }
            // hh
#pragma unroll
            for (int mt = 0; mt < 2; mt++)
#pragma unroll
                for (int nt = 0; nt < 8; nt++) mma_bf16(acc[mt][nt], aH[mt], bF[nt]);
            // lh
#pragma unroll
            for (int mt = 0; mt < 2; mt++)
#pragma unroll
                for (int nt = 0; nt < 8; nt++) mma_bf16(acc[mt][nt], aL[mt], bF[nt]);
            // hl
#pragma unroll
            for (int mt = 0; mt < 2; mt++)
#pragma unroll
                for (int nt = 0; nt < 8; nt++) mma_bf16(acc[mt][nt], aH[mt], bL[nt]);
        }
    }

    // ---- epilogue ----
#pragma unroll
    for (int mt = 0; mt < 2; mt++) {
#pragma unroll
        for (int half = 0; half < 2; half++) {
            const int m = m0 + mr + mt*16 + (lane >> 2) + half*8;
#pragma unroll
            for (int nt = 0; nt < 8; nt++) {
                const int n = n0 + nc0 + nt*8 + (lane & 3)*2;
                const float c0 = acc[mt][nt][half*2 + 0];
                const float c1 = acc[mt][nt][half*2 + 1];
                if (MODE == 0) {
                    const int bb  = m >> 11;
                    const int t   = m & 2047;
                    const int mat = n >> 10;
                    const int np  = n & 1023;
                    const float sc = (mat == 0) ? 0.125f : 1.0f;
                    uint32_t hi, lo;
                    split2(c0*sc, c1*sc, hi, lo);
                    __nv_bfloat16* ph = (mat == 0) ? qh : ((mat == 1) ? kh : vh);
                    __nv_bfloat16* pl = (mat == 0) ? ql : ((mat == 1) ? kl : vl);
                    size_t idx = ((size_t)(bb*NH + (np >> 6)) * TSEQ + t) * DH + (np & 63);
                    *(uint32_t*)(ph + idx) = hi;
                    *(uint32_t*)(pl + idx) = lo;
                } else {
                    float* p = out + (size_t)m * DM + n;
                    p[0] = c0 + __ldg(bias + n);
                    p[1] = c1 + __ldg(bias + n + 1);
                }
            }
        }
    }
}

// ---------------------------------------------------------------------------
// Causal flash attention on HMMA, split-bf16, 3-stage KV pipeline
// (prefetch depth 2, wait_group 1). Compute body identical to round 6/10.
// ---------------------------------------------------------------------------
#define AKV   8192
#define ABUF  (4*AKV)                  // 32 KB per stage
#define AQ_OFF (3*ABUF)                // Q after 3 KV stages
#define ATTN_SMEM (3*ABUF + 2*16384)   // 131072

__global__ void __launch_bounds__(256, 1) attn_mma(
    const __nv_bfloat16* __restrict__ qh_g, const __nv_bfloat16* __restrict__ ql_g,
    const __nv_bfloat16* __restrict__ kh_g, const __nv_bfloat16* __restrict__ kl_g,
    const __nv_bfloat16* __restrict__ vh_g, const __nv_bfloat16* __restrict__ vl_g,
    __nv_bfloat16* __restrict__ ch_g, __nv_bfloat16* __restrict__ cl_g)
{
    extern __shared__ char smem[];
    const uint32_t sb = smem_u32(smem);
    const int tid  = threadIdx.x;
    const int lane = tid & 31;
    const int w    = tid >> 5;
    const int qt   = (TSEQ/128 - 1) - blockIdx.x;   // longest blocks first
    const int bh   = blockIdx.y;
    const int g    = lane >> 2;
    const int tig  = lane & 3;
    const int quad = lane >> 3;
    const int l7   = lane & 7;
    const int a_row  = (quad & 1) * 8 + l7;
    const int a_colb = (quad >> 1) * 16;
    const int b_row  = (quad >> 1) * 8 + l7;
    const int b_colb = (quad & 1) * 16;
    const int v_row  = (quad & 1) * 8 + l7;
    const int v_colb = (quad >> 1) * 16;

    const size_t base = (size_t)bh * TSEQ * DH;
    const int rowbase = qt * 128 + w * 16;

    auto issue_kv = [&](int buf, int key0) {
        uint32_t db = sb + buf * ABUF;
        const __nv_bfloat16* srcs[4] = {kh_g, kl_g, vh_g, vl_g};
#pragma unroll
        for (int t4 = 0; t4 < 4; t4++) {
#pragma unroll
            for (int r = 0; r < 2; r++) {
                int id  = tid + 256 * r;
                int row = id >> 3;
                int c16 = id & 7;
                cp_async16(db + t4*AKV + swz(row, c16*16),
                           srcs[t4] + base + (size_t)(key0 + row)*DH + c16*8);
            }
        }
        cp_commit();
    };

    const int NKT = 2*qt + 2;   // >= 2 always

    // prologue: group0 = Q + KV chunk 0; group1 = KV chunk 1
#pragma unroll
    for (int r = 0; r < 4; r++) {
        int id  = tid + 256 * r;
        int row = id >> 3;
        int c16 = id & 7;
        cp_async16(sb + AQ_OFF         + swz(row, c16*16),
                   qh_g + base + (size_t)(qt*128 + row)*DH + c16*8);
        cp_async16(sb + AQ_OFF + 16384 + swz(row, c16*16),
                   ql_g + base + (size_t)(qt*128 + row)*DH + c16*8);
    }
    issue_kv(0, 0);
    issue_kv(1, 64);

    float s[8][4], o[8][4];
    float m_i[2] = {-1e30f, -1e30f}, l_i[2] = {0.0f, 0.0f};
#pragma unroll
    for (int nt = 0; nt < 8; nt++)
#pragma unroll
        for (int e = 0; e < 4; e++) o[nt][e] = 0.0f;
    uint32_t qfh[4][4], qfl[4][4];

    for (int c = 0; c < NKT; c++) {
        if (c + 1 < NKT) cp_wait_1(); else cp_wait_all();
        __syncthreads();
        if (c == 0) {
#pragma unroll
            for (int ks = 0; ks < 4; ks++) {
                ldsm4(qfh[ks], sb + AQ_OFF         + swz(w*16 + a_row, ks*32 + a_colb));
                ldsm4(qfl[ks], sb + AQ_OFF + 16384 + swz(w*16 + a_row, ks*32 + a_colb));
            }
        }
        if (c + 2 < NKT) issue_kv((c + 2) % 3, (c + 2) * 64);

        const int key0 = c * 64;
        if (key0 <= rowbase + 15) {          // warp has unmasked work
            const uint32_t pb = sb + (c % 3) * ABUF;

            // ---- S = Qh*Kh + Ql*Kh + Qh*Kl ----
#pragma unroll
            for (int nt = 0; nt < 8; nt++)
#pragma unroll
                for (int e = 0; e < 4; e++) s[nt][e] = 0.0f;
#pragma unroll
            for (int ks = 0; ks < 4; ks++) {
                uint32_t bK[8][2], t4[4];
#pragma unroll
                for (int ng = 0; ng < 4; ng++) {
                    ldsm4(t4, pb + swz(ng*16 + b_row, ks*32 + b_colb));   // Kh
                    bK[ng*2][0] = t4[0]; bK[ng*2][1] = t4[1];
                    bK[ng*2+1][0] = t4[2]; bK[ng*2+1][1] = t4[3];
                }
#pragma unroll
                for (int nt = 0; nt < 8; nt++) mma_bf16(s[nt], qfh[ks], bK[nt]);
#pragma unroll
                for (int nt = 0; nt < 8; nt++) mma_bf16(s[nt], qfl[ks], bK[nt]);
#pragma unroll
                for (int ng = 0; ng < 4; ng++) {
                    ldsm4(t4, pb + AKV + swz(ng*16 + b_row, ks*32 + b_colb)); // Kl
                    bK[ng*2][0] = t4[0]; bK[ng*2][1] = t4[1];
                    bK[ng*2+1][0] = t4[2]; bK[ng*2+1][1] = t4[3];
                }
#pragma unroll
                for (int nt = 0; nt < 8; nt++) mma_bf16(s[nt], qfh[ks], bK[nt]);
            }

            // ---- causal mask (diagonal chunks only) ----
            if (key0 + 63 > rowbase) {
#pragma unroll
                for (int nt = 0; nt < 8; nt++) {
#pragma unroll
                    for (int e = 0; e < 4; e++) {
                        int col = key0 + nt*8 + 2*tig + (e & 1);
                        int row = rowbase + g + ((e >= 2) ? 8 : 0);
                        if (col > row) s[nt][e] = -1e30f;
                    }
                }
            }

            // ---- online softmax ----
            float rm0 = -1e30f, rm1 = -1e30f;
#pragma unroll
            for (int nt = 0; nt < 8; nt++) {
                rm0 = fmaxf(rm0, fmaxf(s[nt][0], s[nt][1]));
                rm1 = fmaxf(rm1, fmaxf(s[nt][2], s[nt][3]));
            }
            rm0 = fmaxf(rm0, __shfl_xor_sync(0xffffffffu, rm0, 1));
            rm0 = fmaxf(rm0, __shfl_xor_sync(0xffffffffu, rm0, 2));
            rm1 = fmaxf(rm1, __shfl_xor_sync(0xffffffffu, rm1, 1));
            rm1 = fmaxf(rm1, __shfl_xor_sync(0xffffffffu, rm1, 2));
            float mn0 = fmaxf(m_i[0], rm0), mn1 = fmaxf(m_i[1], rm1);
            float al0 = __expf(m_i[0] - mn0), al1 = __expf(m_i[1] - mn1);
            m_i[0] = mn0; m_i[1] = mn1;
            float rs0 = 0.0f, rs1 = 0.0f;
#pragma unroll
            for (int nt = 0; nt < 8; nt++) {
                s[nt][0] = __expf(s[nt][0] - mn0);
                s[nt][1] = __expf(s[nt][1] - mn0);
                s[nt][2] = __expf(s[nt][2] - mn1);
                s[nt][3] = __expf(s[nt][3] - mn1);
                rs0 += s[nt][0] + s[nt][1];
                rs1 += s[nt][2] + s[nt][3];
            }
            rs0 += __shfl_xor_sync(0xffffffffu, rs0, 1);
            rs0 += __shfl_xor_sync(0xffffffffu, rs0, 2);
            rs1 += __shfl_xor_sync(0xffffffffu, rs1, 1);
            rs1 += __shfl_xor_sync(0xffffffffu, rs1, 2);
            l_i[0] = l_i[0]*al0 + rs0;
            l_i[1] = l_i[1]*al1 + rs1;
#pragma unroll
            for (int nt = 0; nt < 8; nt++) {
                o[nt][0] *= al0; o[nt][1] *= al0;
                o[nt][2] *= al1; o[nt][3] *= al1;
            }

            // ---- O += Ph*Vh + Pl*Vh + Ph*Vl ----
#pragma unroll
            for (int ks = 0; ks < 4; ks++) {
                uint32_t ph[4], pl[4];
                split2(s[2*ks][0],   s[2*ks][1],   ph[0], pl[0]);
                split2(s[2*ks][2],   s[2*ks][3],   ph[1], pl[1]);
                split2(s[2*ks+1][0], s[2*ks+1][1], ph[2], pl[2]);
                split2(s[2*ks+1][2], s[2*ks+1][3], ph[3], pl[3]);
                uint32_t bV[8][2], t4[4];
#pragma unroll
                for (int ng = 0; ng < 4; ng++) {
                    ldsm4t(t4, pb + 2*AKV + swz(ks*16 + v_row, ng*32 + v_colb)); // Vh
                    bV[ng*2][0] = t4[0]; bV[ng*2][1] = t4[1];
                    bV[ng*2+1][0] = t4[2]; bV[ng*2+1][1] = t4[3];
                }
#pragma unroll
                for (int nt = 0; nt < 8; nt++) mma_bf16(o[nt], ph, bV[nt]);
#pragma unroll
                for (int nt = 0; nt < 8; nt++) mma_bf16(o[nt], pl, bV[nt]);
#pragma unroll
                for (int ng = 0; ng < 4; ng++) {
                    ldsm4t(t4, pb + 3*AKV + swz(ks*16 + v_row, ng*32 + v_colb)); // Vl
                    bV[ng*2][0] = t4[0]; bV[ng*2][1] = t4[1];
                    bV[ng*2+1][0] = t4[2]; bV[ng*2+1][1] = t4[3];
                }
#pragma unroll
                for (int nt = 0; nt < 8; nt++) mma_bf16(o[nt], ph, bV[nt]);
            }
        }
    }

    // ---- epilogue ----
    const int b_ = bh >> 4;
    const int h  = bh & 15;
    const float inv0 = 1.0f / l_i[0];
    const float inv1 = 1.0f / l_i[1];
    const int t0r = rowbase + g;
    const int t1r = rowbase + g + 8;
#pragma unroll
    for (int nt = 0; nt < 8; nt++) {
        const int col = h*64 + nt*8 + 2*tig;
        uint32_t hi, lo;
        split2(o[nt][0]*inv0, o[nt][1]*inv0, hi, lo);
        size_t i0 = ((size_t)(b_*TSEQ) + t0r) * DM + col;
        *(uint32_t*)(ch_g + i0) = hi;
        *(uint32_t*)(cl_g + i0) = lo;
        split2(o[nt][2]*inv1, o[nt][3]*inv1, hi, lo);
        size_t i1 = ((size_t)(b_*TSEQ) + t1r) * DM + col;
        *(uint32_t*)(ch_g + i1) = hi;
        *(uint32_t*)(cl_g + i1) = lo;
    }
}

// ---------------------------------------------------------------------------
extern "C" void kernel_launch(void* const* d_in, const int* in_sizes, int n_in,
                              void* d_out, int out_size)
{
    const float* x  = (const float*)d_in[0];
    const float* Wq = (const float*)d_in[1];
    const float* Wk = (const float*)d_in[2];
    const float* Wv = (const float*)d_in[3];
    const float* Wo = (const float*)d_in[4];
    const float* bo = (const float*)d_in[5];
    float* out = (float*)d_out;

    __nv_bfloat16 *qh, *ql, *kh, *kl, *vh, *vl;
    __nv_bfloat16 *xh, *xl, *wh, *wl, *ch, *cl, *woh, *wol;
    cudaGetSymbolAddress((void**)&qh,  g_qh);
    cudaGetSymbolAddress((void**)&ql,  g_ql);
    cudaGetSymbolAddress((void**)&kh,  g_kh);
    cudaGetSymbolAddress((void**)&kl,  g_kl);
    cudaGetSymbolAddress((void**)&vh,  g_vh);
    cudaGetSymbolAddress((void**)&vl,  g_vl);
    cudaGetSymbolAddress((void**)&xh,  g_xh);
    cudaGetSymbolAddress((void**)&xl,  g_xl);
    cudaGetSymbolAddress((void**)&wh,  g_wh);
    cudaGetSymbolAddress((void**)&wl,  g_wl);
    cudaGetSymbolAddress((void**)&ch,  g_ch);
    cudaGetSymbolAddress((void**)&cl,  g_cl);
    cudaGetSymbolAddress((void**)&woh, g_woh);
    cudaGetSymbolAddress((void**)&wol, g_wol);

    cudaFuncSetAttribute(mma_gemm<0>,
                         cudaFuncAttributeMaxDynamicSharedMemorySize, GEMM_SMEM);
    cudaFuncSetAttribute(mma_gemm<1>,
                         cudaFuncAttributeMaxDynamicSharedMemorySize, GEMM_SMEM);
    cudaFuncSetAttribute(attn_mma,
                         cudaFuncAttributeMaxDynamicSharedMemorySize, ATTN_SMEM);

    // single merged split launch (reference swaps names: q = x@Wk^T, k = x@Wq^T)
    split5_kernel<<<XB + 4*WB, 256>>>(x, Wk, Wq, Wv, Wo,
                                      xh, xl, wh, wl, woh, wol);

    // fused QKV projection (N=3072), bf16 hi/lo epilogue
    mma_gemm<0><<<dim3(3*DM/128, MTOT/128), 256, GEMM_SMEM>>>(
        xh, xl, wh, wl, qh, ql, kh, kl, vh, vl, nullptr, nullptr);

    attn_mma<<<dim3(TSEQ/128, BATCH*NH), 256, ATTN_SMEM>>>(
        qh, ql, kh, kl, vh, vl, ch, cl);

    mma_gemm<1><<<dim3(DM/128, MTOT/128), 256, GEMM_SMEM>>>(
        ch, cl, woh, wol, nullptr, nullptr, nullptr, nullptr, nullptr, nullptr,
        out, bo);
}